// round 1
// baseline (speedup 1.0000x reference)
#include <cuda_runtime.h>
#include <cuda_bf16.h>
#include <math.h>

// Problem constants
#define BATCH 2
#define SEQ   2048
#define DMODEL 2048
#define NHEADS 16
#define DHEAD 128
#define MROWS (BATCH*SEQ)        // 4096
#define NQKV  (3*DMODEL)         // 6144

// Scratch (device globals; no runtime allocation allowed)
__device__ float g_q [ (size_t)MROWS * DMODEL ];   // q pre-norm -> normalized in place
__device__ float g_kn[ (size_t)MROWS * DMODEL ];   // normalized k
__device__ float g_z [ (size_t)MROWS * DMODEL ];   // attention output (b,s,h*dh)

// ---------------------------------------------------------------------------
// SGEMM: C[m,n] = sum_k A[m,k]*B[n,k] + bias[n]
// BM=BN=128, BK=16, 256 threads, 8x8 per-thread micro-tile.
// mode 0: single output C0 (ldc = N)
// mode 1: QKV routing: n<2048 -> C0 (q scratch), <4096 -> C1 (k out), else C2 (v out)
// ---------------------------------------------------------------------------
__global__ __launch_bounds__(256, 2)
void sgemm_kernel(const float* __restrict__ A, const float* __restrict__ B,
                  const float* __restrict__ bias,
                  float* __restrict__ C0, float* __restrict__ C1, float* __restrict__ C2,
                  int M, int N, int K, int mode)
{
    const int BM = 128, BN = 128, BK = 16;
    __shared__ float As[BK][BM + 4];
    __shared__ float Bs[BK][BN + 4];

    const int tid = threadIdx.x;
    const int tx = tid & 15;        // 0..15
    const int ty = tid >> 4;        // 0..15
    const int m0 = blockIdx.y * BM;
    const int n0 = blockIdx.x * BN;

    float acc[8][8];
#pragma unroll
    for (int i = 0; i < 8; i++)
#pragma unroll
        for (int j = 0; j < 8; j++) acc[i][j] = 0.f;

    for (int k0 = 0; k0 < K; k0 += BK) {
        // Load A and B tiles (each 128 rows x 16 cols), transposed into smem.
#pragma unroll
        for (int it = 0; it < 2; it++) {
            int li  = tid + it * 256;      // 0..511
            int row = li >> 2;             // 0..127
            int c4  = li & 3;              // 0..3
            float4 a = *(const float4*)(A + (size_t)(m0 + row) * K + k0 + c4 * 4);
            As[c4*4+0][row] = a.x;
            As[c4*4+1][row] = a.y;
            As[c4*4+2][row] = a.z;
            As[c4*4+3][row] = a.w;
            float4 b = *(const float4*)(B + (size_t)(n0 + row) * K + k0 + c4 * 4);
            Bs[c4*4+0][row] = b.x;
            Bs[c4*4+1][row] = b.y;
            Bs[c4*4+2][row] = b.z;
            Bs[c4*4+3][row] = b.w;
        }
        __syncthreads();

#pragma unroll
        for (int k = 0; k < BK; k++) {
            float ar[8], br[8];
            float4 a0 = *(const float4*)&As[k][ty * 8];
            float4 a1 = *(const float4*)&As[k][ty * 8 + 4];
            float4 b0 = *(const float4*)&Bs[k][tx * 8];
            float4 b1 = *(const float4*)&Bs[k][tx * 8 + 4];
            ar[0]=a0.x; ar[1]=a0.y; ar[2]=a0.z; ar[3]=a0.w;
            ar[4]=a1.x; ar[5]=a1.y; ar[6]=a1.z; ar[7]=a1.w;
            br[0]=b0.x; br[1]=b0.y; br[2]=b0.z; br[3]=b0.w;
            br[4]=b1.x; br[5]=b1.y; br[6]=b1.z; br[7]=b1.w;
#pragma unroll
            for (int i = 0; i < 8; i++)
#pragma unroll
                for (int j = 0; j < 8; j++)
                    acc[i][j] = fmaf(ar[i], br[j], acc[i][j]);
        }
        __syncthreads();
    }

    // Epilogue
#pragma unroll
    for (int i = 0; i < 8; i++) {
        size_t m = m0 + ty * 8 + i;
#pragma unroll
        for (int j = 0; j < 8; j++) {
            int n = n0 + tx * 8 + j;
            float v = acc[i][j] + bias[n];
            if (mode == 0) {
                C0[m * (size_t)N + n] = v;
            } else {
                if (n < DMODEL)            C0[m * (size_t)DMODEL + n] = v;
                else if (n < 2 * DMODEL)   C1[m * (size_t)DMODEL + (n - DMODEL)] = v;
                else                       C2[m * (size_t)DMODEL + (n - 2 * DMODEL)] = v;
            }
        }
    }
}

// ---------------------------------------------------------------------------
// RMS norm per head (128 elems). grid.x = MROWS*NHEADS, grid.y: 0 = q, 1 = k.
// ---------------------------------------------------------------------------
__global__ void rmsnorm_kernel(const float* __restrict__ qin, float* __restrict__ qout,
                               const float* __restrict__ kin, float* __restrict__ kout,
                               const float* __restrict__ wq, const float* __restrict__ wk)
{
    const float* in;  float* out;  const float* w;
    if (blockIdx.y == 0) { in = qin; out = qout; w = wq; }
    else                 { in = kin; out = kout; w = wk; }

    size_t base = (size_t)blockIdx.x * DHEAD;
    int t = threadIdx.x;
    float v = in[base + t];
    float ss = v * v;
#pragma unroll
    for (int o = 16; o > 0; o >>= 1) ss += __shfl_xor_sync(0xffffffffu, ss, o);

    __shared__ float sred[4];
    int wid = t >> 5, lane = t & 31;
    if (lane == 0) sred[wid] = ss;
    __syncthreads();
    float tot = sred[0] + sred[1] + sred[2] + sred[3];
    float inv = rsqrtf(tot * (1.0f / DHEAD) + 1e-6f);
    out[base + t] = v * inv * w[t];
}

// ---------------------------------------------------------------------------
// Flash attention (non-causal, scale = 1.0), fp32.
// grid = (SEQ/64, NHEADS, BATCH), 256 threads.
// Per CTA: 64 q-rows, loop over 32 key tiles of 64.
// Thread map: tx=tid&15, ty=tid>>4. S phase: thread owns 4 q-rows x 4 k-cols.
// PV phase: thread owns 4 q-rows x 8 v-cols.
// ---------------------------------------------------------------------------
#define ATT_PITCH 132          // floats per row of Q/K/V smem tiles
#define PS_PITCH  68

__global__ __launch_bounds__(256, 1)
void attn_kernel(const float* __restrict__ Qn, const float* __restrict__ Kn,
                 const float* __restrict__ V, float* __restrict__ Z)
{
    extern __shared__ float sm[];
    float* Qs = sm;
    float* Ks = Qs + 64 * ATT_PITCH;
    float* Vs = Ks + 64 * ATT_PITCH;
    float* Ps = Vs + 64 * ATT_PITCH;

    const int tid = threadIdx.x;
    const int tx = tid & 15;
    const int ty = tid >> 4;
    const int b = blockIdx.z;
    const int h = blockIdx.y;
    const int q0 = blockIdx.x * 64;
    const size_t rowBase = (size_t)b * SEQ;     // global row = rowBase + s
    const int colBase = h * DHEAD;              // column within [*, 2048]

    // Load Q tile: 64 rows x 128 cols = 2048 float4, 8 per thread
#pragma unroll
    for (int it = 0; it < 8; it++) {
        int li = tid + it * 256;
        int r  = li >> 5;             // 0..63
        int c4 = li & 31;             // 0..31
        float4 qv = *(const float4*)(Qn + (rowBase + q0 + r) * DMODEL + colBase + c4 * 4);
        *(float4*)(Qs + r * ATT_PITCH + c4 * 4) = qv;
    }

    float m_i[4], l_i[4], accO[4][8];
#pragma unroll
    for (int i = 0; i < 4; i++) { m_i[i] = -1e30f; l_i[i] = 0.f; }
#pragma unroll
    for (int i = 0; i < 4; i++)
#pragma unroll
        for (int j = 0; j < 8; j++) accO[i][j] = 0.f;

    for (int jt = 0; jt < SEQ / 64; jt++) {
        __syncthreads();   // prev PV done before overwriting tiles
        int kr0 = jt * 64;
#pragma unroll
        for (int it = 0; it < 8; it++) {
            int li = tid + it * 256;
            int r  = li >> 5;
            int c4 = li & 31;
            float4 kv = *(const float4*)(Kn + (rowBase + kr0 + r) * DMODEL + colBase + c4 * 4);
            *(float4*)(Ks + r * ATT_PITCH + c4 * 4) = kv;
            float4 vv = *(const float4*)(V  + (rowBase + kr0 + r) * DMODEL + colBase + c4 * 4);
            *(float4*)(Vs + r * ATT_PITCH + c4 * 4) = vv;
        }
        __syncthreads();

        // S = Q K^T  (4x4 per thread)
        float s[4][4];
#pragma unroll
        for (int i = 0; i < 4; i++)
#pragma unroll
            for (int j = 0; j < 4; j++) s[i][j] = 0.f;

#pragma unroll 4
        for (int d4 = 0; d4 < 32; d4++) {
            float4 qv[4], kv[4];
#pragma unroll
            for (int i = 0; i < 4; i++)
                qv[i] = *(const float4*)(Qs + (ty * 4 + i) * ATT_PITCH + d4 * 4);
#pragma unroll
            for (int j = 0; j < 4; j++)
                kv[j] = *(const float4*)(Ks + (tx * 4 + j) * ATT_PITCH + d4 * 4);
#pragma unroll
            for (int i = 0; i < 4; i++)
#pragma unroll
                for (int j = 0; j < 4; j++) {
                    s[i][j] = fmaf(qv[i].x, kv[j].x, s[i][j]);
                    s[i][j] = fmaf(qv[i].y, kv[j].y, s[i][j]);
                    s[i][j] = fmaf(qv[i].z, kv[j].z, s[i][j]);
                    s[i][j] = fmaf(qv[i].w, kv[j].w, s[i][j]);
                }
        }

        // Online softmax update per owned row
#pragma unroll
        for (int i = 0; i < 4; i++) {
            float rmax = fmaxf(fmaxf(s[i][0], s[i][1]), fmaxf(s[i][2], s[i][3]));
#pragma unroll
            for (int o = 8; o > 0; o >>= 1)
                rmax = fmaxf(rmax, __shfl_xor_sync(0xffffffffu, rmax, o));
            float mnew = fmaxf(m_i[i], rmax);
            float scale = __expf(m_i[i] - mnew);
            float rs = 0.f;
#pragma unroll
            for (int j = 0; j < 4; j++) {
                float p = __expf(s[i][j] - mnew);
                s[i][j] = p;
                rs += p;
            }
#pragma unroll
            for (int o = 8; o > 0; o >>= 1)
                rs += __shfl_xor_sync(0xffffffffu, rs, o);
            l_i[i] = l_i[i] * scale + rs;
            m_i[i] = mnew;
#pragma unroll
            for (int j = 0; j < 8; j++) accO[i][j] *= scale;
            // stash P
#pragma unroll
            for (int j = 0; j < 4; j++)
                Ps[(ty * 4 + i) * PS_PITCH + tx * 4 + j] = s[i][j];
        }
        __syncthreads();

        // O += P V   (thread: 4 rows x 8 cols, cols = tx*8..)
#pragma unroll 4
        for (int kc = 0; kc < 64; kc++) {
            float4 v0 = *(const float4*)(Vs + kc * ATT_PITCH + tx * 8);
            float4 v1 = *(const float4*)(Vs + kc * ATT_PITCH + tx * 8 + 4);
#pragma unroll
            for (int i = 0; i < 4; i++) {
                float p = Ps[(ty * 4 + i) * PS_PITCH + kc];
                accO[i][0] = fmaf(p, v0.x, accO[i][0]);
                accO[i][1] = fmaf(p, v0.y, accO[i][1]);
                accO[i][2] = fmaf(p, v0.z, accO[i][2]);
                accO[i][3] = fmaf(p, v0.w, accO[i][3]);
                accO[i][4] = fmaf(p, v1.x, accO[i][4]);
                accO[i][5] = fmaf(p, v1.y, accO[i][5]);
                accO[i][6] = fmaf(p, v1.z, accO[i][6]);
                accO[i][7] = fmaf(p, v1.w, accO[i][7]);
            }
        }
    }

    // Finalize: O / l, write to Z
#pragma unroll
    for (int i = 0; i < 4; i++) {
        float invl = 1.0f / l_i[i];
        size_t row = rowBase + q0 + ty * 4 + i;
        float* dst = Z + row * DMODEL + colBase + tx * 8;
#pragma unroll
        for (int j = 0; j < 8; j++) dst[j] = accO[i][j] * invl;
    }
}

// ---------------------------------------------------------------------------
extern "C" void kernel_launch(void* const* d_in, const int* in_sizes, int n_in,
                              void* d_out, int out_size)
{
    const float* x     = (const float*)d_in[0];
    const float* W_qkv = (const float*)d_in[1];
    const float* b_qkv = (const float*)d_in[2];
    const float* W_o   = (const float*)d_in[3];
    const float* b_o   = (const float*)d_in[4];
    const float* wq    = (const float*)d_in[5];
    const float* wk    = (const float*)d_in[6];

    float* out   = (float*)d_out;                               // [4096,2048]
    float* k_out = out   + (size_t)MROWS * DMODEL;              // [4096,2048]
    float* v_out = k_out + (size_t)MROWS * DMODEL;              // [4096,2048]

    float *qPtr, *knPtr, *zPtr;
    cudaGetSymbolAddress((void**)&qPtr,  g_q);
    cudaGetSymbolAddress((void**)&knPtr, g_kn);
    cudaGetSymbolAddress((void**)&zPtr,  g_z);

    // 1) QKV projection: [4096,2048] x [6144,2048]^T
    {
        dim3 grid(NQKV / 128, MROWS / 128);
        sgemm_kernel<<<grid, 256>>>(x, W_qkv, b_qkv, qPtr, k_out, v_out,
                                    MROWS, NQKV, DMODEL, 1);
    }

    // 2) RMS norm q (in place) and k (-> g_kn)
    {
        dim3 grid(MROWS * NHEADS, 2);
        rmsnorm_kernel<<<grid, DHEAD>>>(qPtr, qPtr, k_out, knPtr, wq, wk);
    }

    // 3) Attention
    {
        int smem = (3 * 64 * ATT_PITCH + 64 * PS_PITCH) * sizeof(float);
        cudaFuncSetAttribute(attn_kernel, cudaFuncAttributeMaxDynamicSharedMemorySize, smem);
        dim3 grid(SEQ / 64, NHEADS, BATCH);
        attn_kernel<<<grid, 256, smem>>>(qPtr, knPtr, v_out, zPtr);
    }

    // 4) Output projection: [4096,2048] x [2048,2048]^T
    {
        dim3 grid(DMODEL / 128, MROWS / 128);
        sgemm_kernel<<<grid, 256>>>(zPtr, W_o, b_o, out, nullptr, nullptr,
                                    MROWS, DMODEL, DMODEL, 0);
    }
}

// round 2
// speedup vs baseline: 1.0005x; 1.0005x over previous
#include <cuda_runtime.h>
#include <cuda_bf16.h>
#include <math.h>

// Problem constants
#define BATCH 2
#define SEQ   2048
#define DMODEL 2048
#define NHEADS 16
#define DHEAD 128
#define MROWS (BATCH*SEQ)        // 4096
#define NQKV  (3*DMODEL)         // 6144

// Scratch (device globals; no runtime allocation allowed)
__device__ float g_q [ (size_t)MROWS * DMODEL ];   // q pre-norm -> normalized in place
__device__ float g_kn[ (size_t)MROWS * DMODEL ];   // normalized k
__device__ float g_z [ (size_t)MROWS * DMODEL ];   // attention output (b,s,h*dh)

// ---------------------------------------------------------------------------
// SGEMM: C[m,n] = sum_k A[m,k]*B[n,k] + bias[n]
// BM=BN=128, BK=16, 256 threads, 8x8 per-thread micro-tile.
// mode 0: single output C0 (ldc = N)
// mode 1: QKV routing: n<2048 -> C0 (q scratch), <4096 -> C1 (k out), else C2 (v out)
// ---------------------------------------------------------------------------
__global__ __launch_bounds__(256, 2)
void sgemm_kernel(const float* __restrict__ A, const float* __restrict__ B,
                  const float* __restrict__ bias,
                  float* __restrict__ C0, float* __restrict__ C1, float* __restrict__ C2,
                  int M, int N, int K, int mode)
{
    const int BM = 128, BN = 128, BK = 16;
    __shared__ float As[BK][BM + 4];
    __shared__ float Bs[BK][BN + 4];

    const int tid = threadIdx.x;
    const int tx = tid & 15;        // 0..15
    const int ty = tid >> 4;        // 0..15
    const int m0 = blockIdx.y * BM;
    const int n0 = blockIdx.x * BN;

    float acc[8][8];
#pragma unroll
    for (int i = 0; i < 8; i++)
#pragma unroll
        for (int j = 0; j < 8; j++) acc[i][j] = 0.f;

    for (int k0 = 0; k0 < K; k0 += BK) {
        // Load A and B tiles (each 128 rows x 16 cols), transposed into smem.
#pragma unroll
        for (int it = 0; it < 2; it++) {
            int li  = tid + it * 256;      // 0..511
            int row = li >> 2;             // 0..127
            int c4  = li & 3;              // 0..3
            float4 a = *(const float4*)(A + (size_t)(m0 + row) * K + k0 + c4 * 4);
            As[c4*4+0][row] = a.x;
            As[c4*4+1][row] = a.y;
            As[c4*4+2][row] = a.z;
            As[c4*4+3][row] = a.w;
            float4 b = *(const float4*)(B + (size_t)(n0 + row) * K + k0 + c4 * 4);
            Bs[c4*4+0][row] = b.x;
            Bs[c4*4+1][row] = b.y;
            Bs[c4*4+2][row] = b.z;
            Bs[c4*4+3][row] = b.w;
        }
        __syncthreads();

#pragma unroll
        for (int k = 0; k < BK; k++) {
            float ar[8], br[8];
            float4 a0 = *(const float4*)&As[k][ty * 8];
            float4 a1 = *(const float4*)&As[k][ty * 8 + 4];
            float4 b0 = *(const float4*)&Bs[k][tx * 8];
            float4 b1 = *(const float4*)&Bs[k][tx * 8 + 4];
            ar[0]=a0.x; ar[1]=a0.y; ar[2]=a0.z; ar[3]=a0.w;
            ar[4]=a1.x; ar[5]=a1.y; ar[6]=a1.z; ar[7]=a1.w;
            br[0]=b0.x; br[1]=b0.y; br[2]=b0.z; br[3]=b0.w;
            br[4]=b1.x; br[5]=b1.y; br[6]=b1.z; br[7]=b1.w;
#pragma unroll
            for (int i = 0; i < 8; i++)
#pragma unroll
                for (int j = 0; j < 8; j++)
                    acc[i][j] = fmaf(ar[i], br[j], acc[i][j]);
        }
        __syncthreads();
    }

    // Epilogue
#pragma unroll
    for (int i = 0; i < 8; i++) {
        size_t m = m0 + ty * 8 + i;
#pragma unroll
        for (int j = 0; j < 8; j++) {
            int n = n0 + tx * 8 + j;
            float v = acc[i][j] + bias[n];
            if (mode == 0) {
                C0[m * (size_t)N + n] = v;
            } else {
                if (n < DMODEL)            C0[m * (size_t)DMODEL + n] = v;
                else if (n < 2 * DMODEL)   C1[m * (size_t)DMODEL + (n - DMODEL)] = v;
                else                       C2[m * (size_t)DMODEL + (n - 2 * DMODEL)] = v;
            }
        }
    }
}

// ---------------------------------------------------------------------------
// RMS norm per head (128 elems). grid.x = MROWS*NHEADS, grid.y: 0 = q, 1 = k.
// ---------------------------------------------------------------------------
__global__ void rmsnorm_kernel(const float* __restrict__ qin, float* __restrict__ qout,
                               const float* __restrict__ kin, float* __restrict__ kout,
                               const float* __restrict__ wq, const float* __restrict__ wk)
{
    const float* in;  float* out;  const float* w;
    if (blockIdx.y == 0) { in = qin; out = qout; w = wq; }
    else                 { in = kin; out = kout; w = wk; }

    size_t base = (size_t)blockIdx.x * DHEAD;
    int t = threadIdx.x;
    float v = in[base + t];
    float ss = v * v;
#pragma unroll
    for (int o = 16; o > 0; o >>= 1) ss += __shfl_xor_sync(0xffffffffu, ss, o);

    __shared__ float sred[4];
    int wid = t >> 5, lane = t & 31;
    if (lane == 0) sred[wid] = ss;
    __syncthreads();
    float tot = sred[0] + sred[1] + sred[2] + sred[3];
    float inv = rsqrtf(tot * (1.0f / DHEAD) + 1e-6f);
    out[base + t] = v * inv * w[t];
}

// ---------------------------------------------------------------------------
// Flash attention (non-causal, scale = 1.0), fp32.
// grid = (SEQ/64, NHEADS, BATCH), 256 threads.
// Per CTA: 64 q-rows, loop over 32 key tiles of 64.
// Thread map: tx=tid&15, ty=tid>>4. S phase: thread owns 4 q-rows x 4 k-cols.
// PV phase: thread owns 4 q-rows x 8 v-cols.
// ---------------------------------------------------------------------------
#define ATT_PITCH 132          // floats per row of Q/K/V smem tiles
#define PS_PITCH  68

__global__ __launch_bounds__(256, 1)
void attn_kernel(const float* __restrict__ Qn, const float* __restrict__ Kn,
                 const float* __restrict__ V, float* __restrict__ Z)
{
    extern __shared__ float sm[];
    float* Qs = sm;
    float* Ks = Qs + 64 * ATT_PITCH;
    float* Vs = Ks + 64 * ATT_PITCH;
    float* Ps = Vs + 64 * ATT_PITCH;

    const int tid = threadIdx.x;
    const int tx = tid & 15;
    const int ty = tid >> 4;
    const int b = blockIdx.z;
    const int h = blockIdx.y;
    const int q0 = blockIdx.x * 64;
    const size_t rowBase = (size_t)b * SEQ;     // global row = rowBase + s
    const int colBase = h * DHEAD;              // column within [*, 2048]

    // Load Q tile: 64 rows x 128 cols = 2048 float4, 8 per thread
#pragma unroll
    for (int it = 0; it < 8; it++) {
        int li = tid + it * 256;
        int r  = li >> 5;             // 0..63
        int c4 = li & 31;             // 0..31
        float4 qv = *(const float4*)(Qn + (rowBase + q0 + r) * DMODEL + colBase + c4 * 4);
        *(float4*)(Qs + r * ATT_PITCH + c4 * 4) = qv;
    }

    float m_i[4], l_i[4], accO[4][8];
#pragma unroll
    for (int i = 0; i < 4; i++) { m_i[i] = -1e30f; l_i[i] = 0.f; }
#pragma unroll
    for (int i = 0; i < 4; i++)
#pragma unroll
        for (int j = 0; j < 8; j++) accO[i][j] = 0.f;

    for (int jt = 0; jt < SEQ / 64; jt++) {
        __syncthreads();   // prev PV done before overwriting tiles
        int kr0 = jt * 64;
#pragma unroll
        for (int it = 0; it < 8; it++) {
            int li = tid + it * 256;
            int r  = li >> 5;
            int c4 = li & 31;
            float4 kv = *(const float4*)(Kn + (rowBase + kr0 + r) * DMODEL + colBase + c4 * 4);
            *(float4*)(Ks + r * ATT_PITCH + c4 * 4) = kv;
            float4 vv = *(const float4*)(V  + (rowBase + kr0 + r) * DMODEL + colBase + c4 * 4);
            *(float4*)(Vs + r * ATT_PITCH + c4 * 4) = vv;
        }
        __syncthreads();

        // S = Q K^T  (4x4 per thread)
        float s[4][4];
#pragma unroll
        for (int i = 0; i < 4; i++)
#pragma unroll
            for (int j = 0; j < 4; j++) s[i][j] = 0.f;

#pragma unroll 4
        for (int d4 = 0; d4 < 32; d4++) {
            float4 qv[4], kv[4];
#pragma unroll
            for (int i = 0; i < 4; i++)
                qv[i] = *(const float4*)(Qs + (ty * 4 + i) * ATT_PITCH + d4 * 4);
#pragma unroll
            for (int j = 0; j < 4; j++)
                kv[j] = *(const float4*)(Ks + (tx * 4 + j) * ATT_PITCH + d4 * 4);
#pragma unroll
            for (int i = 0; i < 4; i++)
#pragma unroll
                for (int j = 0; j < 4; j++) {
                    s[i][j] = fmaf(qv[i].x, kv[j].x, s[i][j]);
                    s[i][j] = fmaf(qv[i].y, kv[j].y, s[i][j]);
                    s[i][j] = fmaf(qv[i].z, kv[j].z, s[i][j]);
                    s[i][j] = fmaf(qv[i].w, kv[j].w, s[i][j]);
                }
        }

        // Online softmax update per owned row
#pragma unroll
        for (int i = 0; i < 4; i++) {
            float rmax = fmaxf(fmaxf(s[i][0], s[i][1]), fmaxf(s[i][2], s[i][3]));
#pragma unroll
            for (int o = 8; o > 0; o >>= 1)
                rmax = fmaxf(rmax, __shfl_xor_sync(0xffffffffu, rmax, o));
            float mnew = fmaxf(m_i[i], rmax);
            float scale = __expf(m_i[i] - mnew);
            float rs = 0.f;
#pragma unroll
            for (int j = 0; j < 4; j++) {
                float p = __expf(s[i][j] - mnew);
                s[i][j] = p;
                rs += p;
            }
#pragma unroll
            for (int o = 8; o > 0; o >>= 1)
                rs += __shfl_xor_sync(0xffffffffu, rs, o);
            l_i[i] = l_i[i] * scale + rs;
            m_i[i] = mnew;
#pragma unroll
            for (int j = 0; j < 8; j++) accO[i][j] *= scale;
            // stash P
#pragma unroll
            for (int j = 0; j < 4; j++)
                Ps[(ty * 4 + i) * PS_PITCH + tx * 4 + j] = s[i][j];
        }
        __syncthreads();

        // O += P V   (thread: 4 rows x 8 cols, cols = tx*8..)
#pragma unroll 4
        for (int kc = 0; kc < 64; kc++) {
            float4 v0 = *(const float4*)(Vs + kc * ATT_PITCH + tx * 8);
            float4 v1 = *(const float4*)(Vs + kc * ATT_PITCH + tx * 8 + 4);
#pragma unroll
            for (int i = 0; i < 4; i++) {
                float p = Ps[(ty * 4 + i) * PS_PITCH + kc];
                accO[i][0] = fmaf(p, v0.x, accO[i][0]);
                accO[i][1] = fmaf(p, v0.y, accO[i][1]);
                accO[i][2] = fmaf(p, v0.z, accO[i][2]);
                accO[i][3] = fmaf(p, v0.w, accO[i][3]);
                accO[i][4] = fmaf(p, v1.x, accO[i][4]);
                accO[i][5] = fmaf(p, v1.y, accO[i][5]);
                accO[i][6] = fmaf(p, v1.z, accO[i][6]);
                accO[i][7] = fmaf(p, v1.w, accO[i][7]);
            }
        }
    }

    // Finalize: O / l, write to Z
#pragma unroll
    for (int i = 0; i < 4; i++) {
        float invl = 1.0f / l_i[i];
        size_t row = rowBase + q0 + ty * 4 + i;
        float* dst = Z + row * DMODEL + colBase + tx * 8;
#pragma unroll
        for (int j = 0; j < 8; j++) dst[j] = accO[i][j] * invl;
    }
}

// ---------------------------------------------------------------------------
extern "C" void kernel_launch(void* const* d_in, const int* in_sizes, int n_in,
                              void* d_out, int out_size)
{
    const float* x     = (const float*)d_in[0];
    const float* W_qkv = (const float*)d_in[1];
    const float* b_qkv = (const float*)d_in[2];
    const float* W_o   = (const float*)d_in[3];
    const float* b_o   = (const float*)d_in[4];
    const float* wq    = (const float*)d_in[5];
    const float* wk    = (const float*)d_in[6];

    float* out   = (float*)d_out;                               // [4096,2048]
    float* k_out = out   + (size_t)MROWS * DMODEL;              // [4096,2048]
    float* v_out = k_out + (size_t)MROWS * DMODEL;              // [4096,2048]

    float *qPtr, *knPtr, *zPtr;
    cudaGetSymbolAddress((void**)&qPtr,  g_q);
    cudaGetSymbolAddress((void**)&knPtr, g_kn);
    cudaGetSymbolAddress((void**)&zPtr,  g_z);

    // 1) QKV projection: [4096,2048] x [6144,2048]^T
    {
        dim3 grid(NQKV / 128, MROWS / 128);
        sgemm_kernel<<<grid, 256>>>(x, W_qkv, b_qkv, qPtr, k_out, v_out,
                                    MROWS, NQKV, DMODEL, 1);
    }

    // 2) RMS norm q (in place) and k (-> g_kn)
    {
        dim3 grid(MROWS * NHEADS, 2);
        rmsnorm_kernel<<<grid, DHEAD>>>(qPtr, qPtr, k_out, knPtr, wq, wk);
    }

    // 3) Attention
    {
        int smem = (3 * 64 * ATT_PITCH + 64 * PS_PITCH) * sizeof(float);
        cudaFuncSetAttribute(attn_kernel, cudaFuncAttributeMaxDynamicSharedMemorySize, smem);
        dim3 grid(SEQ / 64, NHEADS, BATCH);
        attn_kernel<<<grid, 256, smem>>>(qPtr, knPtr, v_out, zPtr);
    }

    // 4) Output projection: [4096,2048] x [2048,2048]^T
    {
        dim3 grid(DMODEL / 128, MROWS / 128);
        sgemm_kernel<<<grid, 256>>>(zPtr, W_o, b_o, out, nullptr, nullptr,
                                    MROWS, DMODEL, DMODEL, 0);
    }
}

// round 7
// speedup vs baseline: 2.5346x; 2.5332x over previous
#include <cuda_runtime.h>
#include <cuda_bf16.h>
#include <math.h>
#include <stdint.h>

// Problem constants
#define BATCH 2
#define SEQ   2048
#define DMODEL 2048
#define NHEADS 16
#define DHEAD 128
#define MROWS (BATCH*SEQ)        // 4096
#define NQKV  (3*DMODEL)         // 6144

// Scratch (device globals; no runtime allocation allowed)
__device__ float g_q [ (size_t)MROWS * DMODEL ];   // q pre-norm -> normalized in place
__device__ float g_kn[ (size_t)MROWS * DMODEL ];   // normalized k
__device__ float g_z [ (size_t)MROWS * DMODEL ];   // attention output (b,s,h*dh)

// ---------------------------------------------------------------------------
// mma / ldmatrix helpers (bf16 m16n8k16, fp32 accum)
// ---------------------------------------------------------------------------
__device__ __forceinline__ uint32_t smem_u32(const void* p) {
    return (uint32_t)__cvta_generic_to_shared(p);
}

__device__ __forceinline__ void ldsm_x4(uint32_t addr, uint32_t& r0, uint32_t& r1,
                                        uint32_t& r2, uint32_t& r3) {
    asm volatile("ldmatrix.sync.aligned.m8n8.x4.shared.b16 {%0,%1,%2,%3}, [%4];"
                 : "=r"(r0), "=r"(r1), "=r"(r2), "=r"(r3) : "r"(addr));
}

__device__ __forceinline__ void ldsm_x4_t(uint32_t addr, uint32_t& r0, uint32_t& r1,
                                          uint32_t& r2, uint32_t& r3) {
    asm volatile("ldmatrix.sync.aligned.m8n8.x4.trans.shared.b16 {%0,%1,%2,%3}, [%4];"
                 : "=r"(r0), "=r"(r1), "=r"(r2), "=r"(r3) : "r"(addr));
}

__device__ __forceinline__ void mma16816(float* d, const uint32_t* a, const uint32_t* b) {
    asm volatile(
        "mma.sync.aligned.m16n8k16.row.col.f32.bf16.bf16.f32 "
        "{%0,%1,%2,%3}, {%4,%5,%6,%7}, {%8,%9}, {%0,%1,%2,%3};"
        : "+f"(d[0]), "+f"(d[1]), "+f"(d[2]), "+f"(d[3])
        : "r"(a[0]), "r"(a[1]), "r"(a[2]), "r"(a[3]), "r"(b[0]), "r"(b[1]));
}

// split a float4 into hi/lo bf16 planes (2x bf16x2 stores each)
__device__ __forceinline__ void split4_store(float4 v, __nv_bfloat16* h, __nv_bfloat16* l) {
    __nv_bfloat162 h0 = __floats2bfloat162_rn(v.x, v.y);
    __nv_bfloat162 h1 = __floats2bfloat162_rn(v.z, v.w);
    float2 f0 = __bfloat1622float2(h0);
    float2 f1 = __bfloat1622float2(h1);
    __nv_bfloat162 l0 = __floats2bfloat162_rn(v.x - f0.x, v.y - f0.y);
    __nv_bfloat162 l1 = __floats2bfloat162_rn(v.z - f1.x, v.w - f1.y);
    *(__nv_bfloat162*)(h)     = h0;
    *(__nv_bfloat162*)(h + 2) = h1;
    *(__nv_bfloat162*)(l)     = l0;
    *(__nv_bfloat162*)(l + 2) = l1;
}

__device__ __forceinline__ uint32_t pack_bf16x2(float a, float b) {
    __nv_bfloat162 t = __floats2bfloat162_rn(a, b);
    return *(uint32_t*)&t;
}

// ---------------------------------------------------------------------------
// bf16x3 GEMM: C[m,n] = sum_k A[m,k]*B[n,k] + bias[n]   (near-fp32 accuracy)
// BM=BN=128, BK=32, 256 threads = 8 warps (2m x 4n), warp tile 64x32.
// mode 0: single output C0 (ld = N). mode 1: QKV routing q/k/v.
// ---------------------------------------------------------------------------
#define GP 40   // padded row stride (bf16) for 32-wide K tiles

__global__ __launch_bounds__(256, 1)
void gemm_bf16x3(const float* __restrict__ A, const float* __restrict__ B,
                 const float* __restrict__ bias,
                 float* __restrict__ C0, float* __restrict__ C1, float* __restrict__ C2,
                 int M, int N, int K, int mode)
{
    __shared__ __nv_bfloat16 Ah[128][GP], Al[128][GP], Bh[128][GP], Bl[128][GP];

    const int tid  = threadIdx.x;
    const int wid  = tid >> 5;
    const int lane = tid & 31;
    const int wm   = wid >> 2;       // 0..1
    const int wn   = wid & 3;        // 0..3
    const int m0   = blockIdx.y * 128;
    const int n0   = blockIdx.x * 128;

    float acc[4][4][4];
#pragma unroll
    for (int i = 0; i < 4; i++)
#pragma unroll
        for (int j = 0; j < 4; j++)
#pragma unroll
            for (int r = 0; r < 4; r++) acc[i][j][r] = 0.f;

    const int lrow = tid >> 1;          // 0..127
    const int lcol = (tid & 1) * 16;    // 0 or 16

    float4 ra[4], rb[4];
#pragma unroll
    for (int i = 0; i < 4; i++) {
        ra[i] = *(const float4*)(A + (size_t)(m0 + lrow) * K + lcol + i * 4);
        rb[i] = *(const float4*)(B + (size_t)(n0 + lrow) * K + lcol + i * 4);
    }

    for (int k0 = 0; k0 < K; k0 += 32) {
        // store prefetched tile (split hi/lo)
#pragma unroll
        for (int i = 0; i < 4; i++) {
            split4_store(ra[i], &Ah[lrow][lcol + i * 4], &Al[lrow][lcol + i * 4]);
            split4_store(rb[i], &Bh[lrow][lcol + i * 4], &Bl[lrow][lcol + i * 4]);
        }
        __syncthreads();

        if (k0 + 32 < K) {
#pragma unroll
            for (int i = 0; i < 4; i++) {
                ra[i] = *(const float4*)(A + (size_t)(m0 + lrow) * K + k0 + 32 + lcol + i * 4);
                rb[i] = *(const float4*)(B + (size_t)(n0 + lrow) * K + k0 + 32 + lcol + i * 4);
            }
        }

#pragma unroll
        for (int ks = 0; ks < 2; ks++) {
            const int kk = ks * 16;
            uint32_t afh[4][4], afl[4][4];
#pragma unroll
            for (int mt = 0; mt < 4; mt++) {
                int r = wm * 64 + mt * 16 + (lane & 15);
                int c = kk + ((lane >> 4) * 8);
                ldsm_x4(smem_u32(&Ah[r][c]), afh[mt][0], afh[mt][1], afh[mt][2], afh[mt][3]);
                ldsm_x4(smem_u32(&Al[r][c]), afl[mt][0], afl[mt][1], afl[mt][2], afl[mt][3]);
            }
            uint32_t bfh[4][2], bfl[4][2];
#pragma unroll
            for (int p = 0; p < 2; p++) {
                int r = wn * 32 + p * 16 + (lane & 15);
                int c = kk + ((lane >> 4) * 8);
                uint32_t t0, t1, t2, t3;
                ldsm_x4(smem_u32(&Bh[r][c]), t0, t1, t2, t3);
                bfh[2*p][0] = t0; bfh[2*p][1] = t2;
                bfh[2*p+1][0] = t1; bfh[2*p+1][1] = t3;
                ldsm_x4(smem_u32(&Bl[r][c]), t0, t1, t2, t3);
                bfl[2*p][0] = t0; bfl[2*p][1] = t2;
                bfl[2*p+1][0] = t1; bfl[2*p+1][1] = t3;
            }
#pragma unroll
            for (int mt = 0; mt < 4; mt++)
#pragma unroll
                for (int nt = 0; nt < 4; nt++) {
                    mma16816(acc[mt][nt], afh[mt], bfh[nt]);
                    mma16816(acc[mt][nt], afh[mt], bfl[nt]);
                    mma16816(acc[mt][nt], afl[mt], bfh[nt]);
                }
        }
        __syncthreads();
    }

    // epilogue
#pragma unroll
    for (int mt = 0; mt < 4; mt++)
#pragma unroll
        for (int nt = 0; nt < 4; nt++)
#pragma unroll
            for (int r = 0; r < 4; r++) {
                size_t row = m0 + wm * 64 + mt * 16 + (lane >> 2) + (r >> 1) * 8;
                int    col = n0 + wn * 32 + nt * 8 + (lane & 3) * 2 + (r & 1);
                float v = acc[mt][nt][r] + bias[col];
                if (mode == 0) {
                    C0[row * (size_t)N + col] = v;
                } else {
                    if (col < DMODEL)          C0[row * (size_t)DMODEL + col] = v;
                    else if (col < 2*DMODEL)   C1[row * (size_t)DMODEL + (col - DMODEL)] = v;
                    else                       C2[row * (size_t)DMODEL + (col - 2*DMODEL)] = v;
                }
            }
}

// ---------------------------------------------------------------------------
// RMS norm per head (128 elems). grid.x = MROWS*NHEADS, grid.y: 0 = q, 1 = k.
// ---------------------------------------------------------------------------
__global__ void rmsnorm_kernel(const float* __restrict__ qin, float* __restrict__ qout,
                               const float* __restrict__ kin, float* __restrict__ kout,
                               const float* __restrict__ wq, const float* __restrict__ wk)
{
    const float* in;  float* out;  const float* w;
    if (blockIdx.y == 0) { in = qin; out = qout; w = wq; }
    else                 { in = kin; out = kout; w = wk; }

    size_t base = (size_t)blockIdx.x * DHEAD;
    int t = threadIdx.x;
    float v = in[base + t];
    float ss = v * v;
#pragma unroll
    for (int o = 16; o > 0; o >>= 1) ss += __shfl_xor_sync(0xffffffffu, ss, o);

    __shared__ float sred[4];
    int wid = t >> 5, lane = t & 31;
    if (lane == 0) sred[wid] = ss;
    __syncthreads();
    float tot = sred[0] + sred[1] + sred[2] + sred[3];
    float inv = rsqrtf(tot * (1.0f / DHEAD) + 1e-6f);
    out[base + t] = v * inv * w[t];
}

// ---------------------------------------------------------------------------
// Flash attention with tensor cores (bf16x3 S and PV, fp32 softmax).
// grid = (SEQ/128, NHEADS, BATCH), 256 threads = 8 warps.
// Q tile 128 rows (16 rows/warp), K/V tiles 64 keys, dh = 128.
// ---------------------------------------------------------------------------
#define QP 136   // padded row stride (bf16) for dh=128 tiles

__global__ __launch_bounds__(256, 1)
void attn_tc(const float* __restrict__ Qn, const float* __restrict__ Kn,
             const float* __restrict__ V, float* __restrict__ Z)
{
    extern __shared__ __nv_bfloat16 smx[];
    __nv_bfloat16* Qh = smx;
    __nv_bfloat16* Ql = Qh + 128 * QP;
    __nv_bfloat16* Kh = Ql + 128 * QP;
    __nv_bfloat16* Kl = Kh + 64 * QP;
    __nv_bfloat16* Vh = Kl + 64 * QP;
    __nv_bfloat16* Vl = Vh + 64 * QP;

    const int tid  = threadIdx.x;
    const int wid  = tid >> 5;
    const int lane = tid & 31;
    const int b  = blockIdx.z;
    const int h  = blockIdx.y;
    const int q0 = blockIdx.x * 128;
    const size_t rowBase = (size_t)b * SEQ;
    const int colBase = h * DHEAD;

    // Load Q tile 128x128: thread -> row tid>>1, 64 cols
    {
        int r = tid >> 1;
        int c0 = (tid & 1) * 64;
#pragma unroll
        for (int i = 0; i < 16; i++) {
            float4 qv = *(const float4*)(Qn + (rowBase + q0 + r) * DMODEL + colBase + c0 + i * 4);
            split4_store(qv, Qh + r * QP + c0 + i * 4, Ql + r * QP + c0 + i * 4);
        }
    }

    float m_i[2] = {-1e30f, -1e30f};
    float l_i[2] = {0.f, 0.f};
    float o[16][4];
#pragma unroll
    for (int i = 0; i < 16; i++)
#pragma unroll
        for (int r = 0; r < 4; r++) o[i][r] = 0.f;

    for (int jt = 0; jt < SEQ / 64; jt++) {
        if (jt) __syncthreads();          // previous PV reads complete
        // Load K/V tile 64x128: thread -> row tid>>2, 32 cols each
        {
            int r = tid >> 2;
            int c0 = (tid & 3) * 32;
            size_t grow = (rowBase + jt * 64 + r) * DMODEL + colBase + c0;
#pragma unroll
            for (int i = 0; i < 8; i++) {
                float4 kv = *(const float4*)(Kn + grow + i * 4);
                split4_store(kv, Kh + r * QP + c0 + i * 4, Kl + r * QP + c0 + i * 4);
                float4 vv = *(const float4*)(V + grow + i * 4);
                split4_store(vv, Vh + r * QP + c0 + i * 4, Vl + r * QP + c0 + i * 4);
            }
        }
        __syncthreads();

        // ---- S = Q K^T : warp computes rows [16*wid, 16*wid+16) x 64 keys
        float s[8][4];
#pragma unroll
        for (int i = 0; i < 8; i++)
#pragma unroll
            for (int r = 0; r < 4; r++) s[i][r] = 0.f;

#pragma unroll
        for (int ks = 0; ks < 8; ks++) {
            uint32_t ah[4], al[4];
            {
                int r = wid * 16 + (lane & 15);
                int c = ks * 16 + ((lane >> 4) * 8);
                ldsm_x4(smem_u32(Qh + r * QP + c), ah[0], ah[1], ah[2], ah[3]);
                ldsm_x4(smem_u32(Ql + r * QP + c), al[0], al[1], al[2], al[3]);
            }
#pragma unroll
            for (int p = 0; p < 4; p++) {
                int r = p * 16 + (lane & 15);
                int c = ks * 16 + ((lane >> 4) * 8);
                uint32_t t0, t1, t2, t3;
                uint32_t bh0[2], bh1[2], bl0[2], bl1[2];
                ldsm_x4(smem_u32(Kh + r * QP + c), t0, t1, t2, t3);
                bh0[0] = t0; bh0[1] = t2; bh1[0] = t1; bh1[1] = t3;
                ldsm_x4(smem_u32(Kl + r * QP + c), t0, t1, t2, t3);
                bl0[0] = t0; bl0[1] = t2; bl1[0] = t1; bl1[1] = t3;
                mma16816(s[2*p],   ah, bh0);
                mma16816(s[2*p],   ah, bl0);
                mma16816(s[2*p],   al, bh0);
                mma16816(s[2*p+1], ah, bh1);
                mma16816(s[2*p+1], ah, bl1);
                mma16816(s[2*p+1], al, bh1);
            }
        }

        // ---- online softmax (rows fully inside warp: lanes 4r..4r+3)
#pragma unroll
        for (int half = 0; half < 2; half++) {
            float rmax = -1e30f;
#pragma unroll
            for (int nt = 0; nt < 8; nt++)
                rmax = fmaxf(rmax, fmaxf(s[nt][2*half], s[nt][2*half + 1]));
            rmax = fmaxf(rmax, __shfl_xor_sync(0xffffffffu, rmax, 1));
            rmax = fmaxf(rmax, __shfl_xor_sync(0xffffffffu, rmax, 2));
            float mnew = fmaxf(m_i[half], rmax);
            float scale = __expf(m_i[half] - mnew);
            float rs = 0.f;
#pragma unroll
            for (int nt = 0; nt < 8; nt++) {
                float p0 = __expf(s[nt][2*half]     - mnew);
                float p1 = __expf(s[nt][2*half + 1] - mnew);
                s[nt][2*half]     = p0;
                s[nt][2*half + 1] = p1;
                rs += p0 + p1;
            }
            rs += __shfl_xor_sync(0xffffffffu, rs, 1);
            rs += __shfl_xor_sync(0xffffffffu, rs, 2);
            l_i[half] = l_i[half] * scale + rs;
            m_i[half] = mnew;
#pragma unroll
            for (int nt = 0; nt < 16; nt++) {
                o[nt][2*half]     *= scale;
                o[nt][2*half + 1] *= scale;
            }
        }

        // ---- O += P V  (P fragments built in registers from s accums)
#pragma unroll
        for (int kk = 0; kk < 4; kk++) {
            uint32_t pah[4], pal[4];
            {
                float v0 = s[2*kk][0],   v1 = s[2*kk][1],   v2 = s[2*kk][2],   v3 = s[2*kk][3];
                float w0 = s[2*kk+1][0], w1 = s[2*kk+1][1], w2 = s[2*kk+1][2], w3 = s[2*kk+1][3];
                __nv_bfloat162 h;
                float2 f;
                h = __floats2bfloat162_rn(v0, v1); f = __bfloat1622float2(h);
                pah[0] = *(uint32_t*)&h; { __nv_bfloat162 t = __floats2bfloat162_rn(v0 - f.x, v1 - f.y); pal[0] = *(uint32_t*)&t; }
                h = __floats2bfloat162_rn(v2, v3); f = __bfloat1622float2(h);
                pah[1] = *(uint32_t*)&h; { __nv_bfloat162 t = __floats2bfloat162_rn(v2 - f.x, v3 - f.y); pal[1] = *(uint32_t*)&t; }
                h = __floats2bfloat162_rn(w0, w1); f = __bfloat1622float2(h);
                pah[2] = *(uint32_t*)&h; { __nv_bfloat162 t = __floats2bfloat162_rn(w0 - f.x, w1 - f.y); pal[2] = *(uint32_t*)&t; }
                h = __floats2bfloat162_rn(w2, w3); f = __bfloat1622float2(h);
                pah[3] = *(uint32_t*)&h; { __nv_bfloat162 t = __floats2bfloat162_rn(w2 - f.x, w3 - f.y); pal[3] = *(uint32_t*)&t; }
            }
#pragma unroll
            for (int p = 0; p < 8; p++) {   // pairs of dh n-tiles
                int r = kk * 16 + (lane & 15);
                int c = p * 16 + ((lane >> 4) * 8);
                uint32_t vh0[2], vh1[2], vl0[2], vl1[2];
                uint32_t t0, t1, t2, t3;
                ldsm_x4_t(smem_u32(Vh + r * QP + c), t0, t1, t2, t3);
                vh0[0] = t0; vh0[1] = t1; vh1[0] = t2; vh1[1] = t3;
                ldsm_x4_t(smem_u32(Vl + r * QP + c), t0, t1, t2, t3);
                vl0[0] = t0; vl0[1] = t1; vl1[0] = t2; vl1[1] = t3;
                mma16816(o[2*p],   pah, vh0);
                mma16816(o[2*p],   pah, vl0);
                mma16816(o[2*p],   pal, vh0);
                mma16816(o[2*p+1], pah, vh1);
                mma16816(o[2*p+1], pah, vl1);
                mma16816(o[2*p+1], pal, vh1);
            }
        }
    }

    // finalize
    float invl[2] = {1.f / l_i[0], 1.f / l_i[1]};
#pragma unroll
    for (int half = 0; half < 2; half++) {
        size_t row = rowBase + q0 + wid * 16 + (lane >> 2) + half * 8;
#pragma unroll
        for (int nt = 0; nt < 16; nt++) {
            int col = colBase + nt * 8 + (lane & 3) * 2;
            float2 vv;
            vv.x = o[nt][2*half]     * invl[half];
            vv.y = o[nt][2*half + 1] * invl[half];
            *(float2*)(Z + row * DMODEL + col) = vv;
        }
    }
}

// ---------------------------------------------------------------------------
extern "C" void kernel_launch(void* const* d_in, const int* in_sizes, int n_in,
                              void* d_out, int out_size)
{
    const float* x     = (const float*)d_in[0];
    const float* W_qkv = (const float*)d_in[1];
    const float* b_qkv = (const float*)d_in[2];
    const float* W_o   = (const float*)d_in[3];
    const float* b_o   = (const float*)d_in[4];
    const float* wq    = (const float*)d_in[5];
    const float* wk    = (const float*)d_in[6];

    float* out   = (float*)d_out;                               // [4096,2048]
    float* k_out = out   + (size_t)MROWS * DMODEL;              // [4096,2048]
    float* v_out = k_out + (size_t)MROWS * DMODEL;              // [4096,2048]

    float *qPtr, *knPtr, *zPtr;
    cudaGetSymbolAddress((void**)&qPtr,  g_q);
    cudaGetSymbolAddress((void**)&knPtr, g_kn);
    cudaGetSymbolAddress((void**)&zPtr,  g_z);

    // 1) QKV projection: [4096,2048] x [6144,2048]^T  (bf16x3 tensor GEMM)
    {
        dim3 grid(NQKV / 128, MROWS / 128);
        gemm_bf16x3<<<grid, 256>>>(x, W_qkv, b_qkv, qPtr, k_out, v_out,
                                   MROWS, NQKV, DMODEL, 1);
    }

    // 2) RMS norm q (in place) and k (-> g_kn)
    {
        dim3 grid(MROWS * NHEADS, 2);
        rmsnorm_kernel<<<grid, DHEAD>>>(qPtr, qPtr, k_out, knPtr, wq, wk);
    }

    // 3) Attention (tensor cores)
    {
        int smem = (2 * 128 + 2 * 64 + 2 * 64) * QP * sizeof(__nv_bfloat16);
        cudaFuncSetAttribute(attn_tc, cudaFuncAttributeMaxDynamicSharedMemorySize, smem);
        dim3 grid(SEQ / 128, NHEADS, BATCH);
        attn_tc<<<grid, 256, smem>>>(qPtr, knPtr, v_out, zPtr);
    }

    // 4) Output projection: [4096,2048] x [2048,2048]^T
    {
        dim3 grid(DMODEL / 128, MROWS / 128);
        gemm_bf16x3<<<grid, 256>>>(zPtr, W_o, b_o, out, nullptr, nullptr,
                                   MROWS, DMODEL, DMODEL, 0);
    }
}

// round 8
// speedup vs baseline: 2.7154x; 1.0713x over previous
#include <cuda_runtime.h>
#include <cuda_bf16.h>
#include <math.h>
#include <stdint.h>

// Problem constants
#define BATCH 2
#define SEQ   2048
#define DMODEL 2048
#define NHEADS 16
#define DHEAD 128
#define MROWS (BATCH*SEQ)        // 4096
#define NQKV  (3*DMODEL)         // 6144

// ---------------------------------------------------------------------------
// Scratch (device globals; no runtime allocation allowed). All bf16 hi/lo planes.
// ---------------------------------------------------------------------------
__device__ float g_q [ (size_t)MROWS * DMODEL ];                  // q pre-norm fp32
__device__ __nv_bfloat16 g_xh [ (size_t)MROWS * DMODEL ];
__device__ __nv_bfloat16 g_xl [ (size_t)MROWS * DMODEL ];
__device__ __nv_bfloat16 g_Wqh[ (size_t)NQKV  * DMODEL ];
__device__ __nv_bfloat16 g_Wql[ (size_t)NQKV  * DMODEL ];
__device__ __nv_bfloat16 g_Woh[ (size_t)DMODEL* DMODEL ];
__device__ __nv_bfloat16 g_Wol[ (size_t)DMODEL* DMODEL ];
__device__ __nv_bfloat16 g_qh [ (size_t)MROWS * DMODEL ];
__device__ __nv_bfloat16 g_ql [ (size_t)MROWS * DMODEL ];
__device__ __nv_bfloat16 g_kh [ (size_t)MROWS * DMODEL ];
__device__ __nv_bfloat16 g_kl [ (size_t)MROWS * DMODEL ];
__device__ __nv_bfloat16 g_vh [ (size_t)MROWS * DMODEL ];
__device__ __nv_bfloat16 g_vl [ (size_t)MROWS * DMODEL ];
__device__ __nv_bfloat16 g_zh [ (size_t)MROWS * DMODEL ];
__device__ __nv_bfloat16 g_zl [ (size_t)MROWS * DMODEL ];

// ---------------------------------------------------------------------------
// helpers
// ---------------------------------------------------------------------------
__device__ __forceinline__ uint32_t smem_u32(const void* p) {
    return (uint32_t)__cvta_generic_to_shared(p);
}
__device__ __forceinline__ void cp16(void* dst, const void* src) {
    asm volatile("cp.async.cg.shared.global [%0], [%1], 16;"
                 :: "r"(smem_u32(dst)), "l"(src));
}
__device__ __forceinline__ void cp_commit() { asm volatile("cp.async.commit_group;"); }
template<int N> __device__ __forceinline__ void cp_wait() {
    asm volatile("cp.async.wait_group %0;" :: "n"(N));
}
__device__ __forceinline__ void ldsm_x4(uint32_t addr, uint32_t& r0, uint32_t& r1,
                                        uint32_t& r2, uint32_t& r3) {
    asm volatile("ldmatrix.sync.aligned.m8n8.x4.shared.b16 {%0,%1,%2,%3}, [%4];"
                 : "=r"(r0), "=r"(r1), "=r"(r2), "=r"(r3) : "r"(addr));
}
__device__ __forceinline__ void ldsm_x4_t(uint32_t addr, uint32_t& r0, uint32_t& r1,
                                          uint32_t& r2, uint32_t& r3) {
    asm volatile("ldmatrix.sync.aligned.m8n8.x4.trans.shared.b16 {%0,%1,%2,%3}, [%4];"
                 : "=r"(r0), "=r"(r1), "=r"(r2), "=r"(r3) : "r"(addr));
}
__device__ __forceinline__ void mma16816(float* d, const uint32_t* a, const uint32_t* b) {
    asm volatile(
        "mma.sync.aligned.m16n8k16.row.col.f32.bf16.bf16.f32 "
        "{%0,%1,%2,%3}, {%4,%5,%6,%7}, {%8,%9}, {%0,%1,%2,%3};"
        : "+f"(d[0]), "+f"(d[1]), "+f"(d[2]), "+f"(d[3])
        : "r"(a[0]), "r"(a[1]), "r"(a[2]), "r"(a[3]), "r"(b[0]), "r"(b[1]));
}

// ---------------------------------------------------------------------------
// fp32 -> bf16 hi/lo plane split (elementwise, float4 vectorized)
// ---------------------------------------------------------------------------
__global__ void split_kernel(const float* __restrict__ in,
                             __nv_bfloat16* __restrict__ h,
                             __nv_bfloat16* __restrict__ l, int n4)
{
    int i = blockIdx.x * blockDim.x + threadIdx.x;
    if (i >= n4) return;
    float4 v = ((const float4*)in)[i];
    __nv_bfloat162 h0 = __floats2bfloat162_rn(v.x, v.y);
    __nv_bfloat162 h1 = __floats2bfloat162_rn(v.z, v.w);
    float2 f0 = __bfloat1622float2(h0);
    float2 f1 = __bfloat1622float2(h1);
    __nv_bfloat162 l0 = __floats2bfloat162_rn(v.x - f0.x, v.y - f0.y);
    __nv_bfloat162 l1 = __floats2bfloat162_rn(v.z - f1.x, v.w - f1.y);
    ((__nv_bfloat162*)h)[2*i]   = h0;
    ((__nv_bfloat162*)h)[2*i+1] = h1;
    ((__nv_bfloat162*)l)[2*i]   = l0;
    ((__nv_bfloat162*)l)[2*i+1] = l1;
}

// ---------------------------------------------------------------------------
// bf16x3 GEMM from preconverted planes, 3-stage cp.async pipeline.
// C[m,n] = sum_k A[m,k]*B[n,k] + bias[n]
// BM=BN=128, BK=32, 256 threads = 8 warps (2m x 4n), warp tile 64x32.
// mode 0: C0 (ld=N). mode 1: QKV routing; v additionally emits bf16 planes.
// ---------------------------------------------------------------------------
#define GP 40
#define GSTAGES 3
#define GTSZ (128 * GP)

__global__ __launch_bounds__(256, 1)
void gemm_planes(const __nv_bfloat16* __restrict__ Ah, const __nv_bfloat16* __restrict__ Al,
                 const __nv_bfloat16* __restrict__ Bh, const __nv_bfloat16* __restrict__ Bl,
                 const float* __restrict__ bias,
                 float* __restrict__ C0, float* __restrict__ C1, float* __restrict__ C2,
                 __nv_bfloat16* __restrict__ VH, __nv_bfloat16* __restrict__ VL,
                 int M, int N, int K, int mode)
{
    extern __shared__ __nv_bfloat16 smg[];
    __nv_bfloat16* sAh = smg;
    __nv_bfloat16* sAl = sAh + GSTAGES * GTSZ;
    __nv_bfloat16* sBh = sAl + GSTAGES * GTSZ;
    __nv_bfloat16* sBl = sBh + GSTAGES * GTSZ;

    const int tid  = threadIdx.x;
    const int wid  = tid >> 5;
    const int lane = tid & 31;
    const int wm   = wid >> 2;
    const int wn   = wid & 3;
    const int m0   = blockIdx.y * 128;
    const int n0   = blockIdx.x * 128;

    // load mapping: thread -> row tid>>1, cols (tid&1)*16 + {0,8}
    const int lrow = tid >> 1;
    const int lcol = (tid & 1) * 16;

    float acc[4][4][4];
#pragma unroll
    for (int i = 0; i < 4; i++)
#pragma unroll
        for (int j = 0; j < 4; j++)
#pragma unroll
            for (int r = 0; r < 4; r++) acc[i][j][r] = 0.f;

    const int iters = K / 32;

    auto load_tile = [&](int t, int st) {
        size_t ga = (size_t)(m0 + lrow) * K + t * 32 + lcol;
        size_t gb = (size_t)(n0 + lrow) * K + t * 32 + lcol;
        size_t so = (size_t)st * GTSZ + lrow * GP + lcol;
        cp16(sAh + so,     Ah + ga);
        cp16(sAh + so + 8, Ah + ga + 8);
        cp16(sAl + so,     Al + ga);
        cp16(sAl + so + 8, Al + ga + 8);
        cp16(sBh + so,     Bh + gb);
        cp16(sBh + so + 8, Bh + gb + 8);
        cp16(sBl + so,     Bl + gb);
        cp16(sBl + so + 8, Bl + gb + 8);
    };

    load_tile(0, 0); cp_commit();
    load_tile(1, 1); cp_commit();

    for (int it = 0; it < iters; ++it) {
        if (it + 2 < iters) cp_wait<1>(); else cp_wait<0>();
        __syncthreads();
        if (it + 2 < iters) { load_tile(it + 2, (it + 2) % GSTAGES); cp_commit(); }

        const __nv_bfloat16* tAh = sAh + (size_t)(it % GSTAGES) * GTSZ;
        const __nv_bfloat16* tAl = sAl + (size_t)(it % GSTAGES) * GTSZ;
        const __nv_bfloat16* tBh = sBh + (size_t)(it % GSTAGES) * GTSZ;
        const __nv_bfloat16* tBl = sBl + (size_t)(it % GSTAGES) * GTSZ;

#pragma unroll
        for (int ks = 0; ks < 2; ks++) {
            const int kk = ks * 16;
            uint32_t afh[4][4], afl[4][4];
#pragma unroll
            for (int mt = 0; mt < 4; mt++) {
                int r = wm * 64 + mt * 16 + (lane & 15);
                int c = kk + ((lane >> 4) * 8);
                ldsm_x4(smem_u32(tAh + r * GP + c), afh[mt][0], afh[mt][1], afh[mt][2], afh[mt][3]);
                ldsm_x4(smem_u32(tAl + r * GP + c), afl[mt][0], afl[mt][1], afl[mt][2], afl[mt][3]);
            }
            uint32_t bfh[4][2], bfl[4][2];
#pragma unroll
            for (int p = 0; p < 2; p++) {
                int r = wn * 32 + p * 16 + (lane & 15);
                int c = kk + ((lane >> 4) * 8);
                uint32_t t0, t1, t2, t3;
                ldsm_x4(smem_u32(tBh + r * GP + c), t0, t1, t2, t3);
                bfh[2*p][0] = t0; bfh[2*p][1] = t2;
                bfh[2*p+1][0] = t1; bfh[2*p+1][1] = t3;
                ldsm_x4(smem_u32(tBl + r * GP + c), t0, t1, t2, t3);
                bfl[2*p][0] = t0; bfl[2*p][1] = t2;
                bfl[2*p+1][0] = t1; bfl[2*p+1][1] = t3;
            }
#pragma unroll
            for (int mt = 0; mt < 4; mt++)
#pragma unroll
                for (int nt = 0; nt < 4; nt++) {
                    mma16816(acc[mt][nt], afh[mt], bfh[nt]);
                    mma16816(acc[mt][nt], afh[mt], bfl[nt]);
                    mma16816(acc[mt][nt], afl[mt], bfh[nt]);
                }
        }
    }

    // epilogue
#pragma unroll
    for (int mt = 0; mt < 4; mt++)
#pragma unroll
        for (int nt = 0; nt < 4; nt++)
#pragma unroll
            for (int r = 0; r < 4; r++) {
                size_t row = m0 + wm * 64 + mt * 16 + (lane >> 2) + (r >> 1) * 8;
                int    col = n0 + wn * 32 + nt * 8 + (lane & 3) * 2 + (r & 1);
                float v = acc[mt][nt][r] + bias[col];
                if (mode == 0) {
                    C0[row * (size_t)N + col] = v;
                } else {
                    if (col < DMODEL) {
                        C0[row * (size_t)DMODEL + col] = v;
                    } else if (col < 2 * DMODEL) {
                        C1[row * (size_t)DMODEL + (col - DMODEL)] = v;
                    } else {
                        size_t idx = row * (size_t)DMODEL + (col - 2 * DMODEL);
                        C2[idx] = v;
                        __nv_bfloat16 hh = __float2bfloat16(v);
                        VH[idx] = hh;
                        VL[idx] = __float2bfloat16(v - __bfloat162float(hh));
                    }
                }
            }
}

// ---------------------------------------------------------------------------
// RMS norm per head (128 elems) -> bf16 hi/lo planes.
// grid.x = MROWS*NHEADS, grid.y: 0 = q, 1 = k.
// ---------------------------------------------------------------------------
__global__ void rmsnorm_split(const float* __restrict__ qin, const float* __restrict__ kin,
                              __nv_bfloat16* __restrict__ qh, __nv_bfloat16* __restrict__ ql,
                              __nv_bfloat16* __restrict__ kh, __nv_bfloat16* __restrict__ kl,
                              const float* __restrict__ wq, const float* __restrict__ wk)
{
    const float* in;  __nv_bfloat16 *oh, *ol;  const float* w;
    if (blockIdx.y == 0) { in = qin; oh = qh; ol = ql; w = wq; }
    else                 { in = kin; oh = kh; ol = kl; w = wk; }

    size_t base = (size_t)blockIdx.x * DHEAD;
    int t = threadIdx.x;
    float v = in[base + t];
    float ss = v * v;
#pragma unroll
    for (int o = 16; o > 0; o >>= 1) ss += __shfl_xor_sync(0xffffffffu, ss, o);

    __shared__ float sred[4];
    int wrp = t >> 5, lane = t & 31;
    if (lane == 0) sred[wrp] = ss;
    __syncthreads();
    float tot = sred[0] + sred[1] + sred[2] + sred[3];
    float inv = rsqrtf(tot * (1.0f / DHEAD) + 1e-6f);
    float vn = v * inv * w[t];
    __nv_bfloat16 hh = __float2bfloat16(vn);
    oh[base + t] = hh;
    ol[base + t] = __float2bfloat16(vn - __bfloat162float(hh));
}

// ---------------------------------------------------------------------------
// Flash attention (bf16x3, fp32 softmax) from preconverted planes.
// grid = (SEQ/128, NHEADS, BATCH), 256 threads = 8 warps.
// Q tile 128 rows (16 rows/warp), K/V tiles 64 keys double-buffered via cp.async.
// Writes z directly as bf16 hi/lo planes.
// ---------------------------------------------------------------------------
#define QP 136
#define KVT (64 * QP)

__global__ __launch_bounds__(256, 1)
void attn_tc2(const __nv_bfloat16* __restrict__ Qh_g, const __nv_bfloat16* __restrict__ Ql_g,
              const __nv_bfloat16* __restrict__ Kh_g, const __nv_bfloat16* __restrict__ Kl_g,
              const __nv_bfloat16* __restrict__ Vh_g, const __nv_bfloat16* __restrict__ Vl_g,
              __nv_bfloat16* __restrict__ ZH, __nv_bfloat16* __restrict__ ZL)
{
    extern __shared__ __nv_bfloat16 smx[];
    __nv_bfloat16* Qh = smx;                 // 128*QP
    __nv_bfloat16* Ql = Qh + 128 * QP;
    __nv_bfloat16* Kh = Ql + 128 * QP;       // 2 stages x 64*QP
    __nv_bfloat16* Kl = Kh + 2 * KVT;
    __nv_bfloat16* Vh = Kl + 2 * KVT;
    __nv_bfloat16* Vl = Vh + 2 * KVT;

    const int tid  = threadIdx.x;
    const int wid  = tid >> 5;
    const int lane = tid & 31;
    const int b  = blockIdx.z;
    const int h  = blockIdx.y;
    const int q0 = blockIdx.x * 128;
    const size_t rowBase = (size_t)b * SEQ;
    const int colBase = h * DHEAD;

    // Q tile: 128x128 bf16 x 2 planes, plain vector copies
    {
        int r = tid >> 1;
        int c0 = (tid & 1) * 64;
        size_t g = (rowBase + q0 + r) * DMODEL + colBase + c0;
#pragma unroll
        for (int i = 0; i < 8; i++) {
            *(uint4*)(Qh + r * QP + c0 + i * 8) = *(const uint4*)(Qh_g + g + i * 8);
            *(uint4*)(Ql + r * QP + c0 + i * 8) = *(const uint4*)(Ql_g + g + i * 8);
        }
    }

    auto load_tile = [&](int jt, int st) {
        int kr0 = jt * 64;
#pragma unroll
        for (int i = 0; i < 4; i++) {
            int c = i * 256 + tid;
            int r = c >> 4, col = (c & 15) * 8;
            size_t g = (rowBase + kr0 + r) * DMODEL + colBase + col;
            size_t s = (size_t)st * KVT + r * QP + col;
            cp16(Kh + s, Kh_g + g);
            cp16(Kl + s, Kl_g + g);
            cp16(Vh + s, Vh_g + g);
            cp16(Vl + s, Vl_g + g);
        }
    };

    float m_i[2] = {-1e30f, -1e30f};
    float l_i[2] = {0.f, 0.f};
    float o[16][4];
#pragma unroll
    for (int i = 0; i < 16; i++)
#pragma unroll
        for (int r = 0; r < 4; r++) o[i][r] = 0.f;

    load_tile(0, 0); cp_commit();

    for (int jt = 0; jt < SEQ / 64; jt++) {
        __syncthreads();      // WAR: stage (jt+1)&1 reads (tile jt-1) finished
        if (jt + 1 < SEQ / 64) {
            load_tile(jt + 1, (jt + 1) & 1); cp_commit();
            cp_wait<1>();
        } else {
            cp_wait<0>();
        }
        __syncthreads();      // tile jt visible to all warps (also Q on jt=0)

        const size_t st = (size_t)(jt & 1) * KVT;

        // ---- S = Q K^T : warp rows [16*wid, 16*wid+16) x 64 keys
        float s[8][4];
#pragma unroll
        for (int i = 0; i < 8; i++)
#pragma unroll
            for (int r = 0; r < 4; r++) s[i][r] = 0.f;

#pragma unroll
        for (int ks = 0; ks < 8; ks++) {
            uint32_t ah[4], al[4];
            {
                int r = wid * 16 + (lane & 15);
                int c = ks * 16 + ((lane >> 4) * 8);
                ldsm_x4(smem_u32(Qh + r * QP + c), ah[0], ah[1], ah[2], ah[3]);
                ldsm_x4(smem_u32(Ql + r * QP + c), al[0], al[1], al[2], al[3]);
            }
#pragma unroll
            for (int p = 0; p < 4; p++) {
                int r = p * 16 + (lane & 15);
                int c = ks * 16 + ((lane >> 4) * 8);
                uint32_t t0, t1, t2, t3;
                uint32_t bh0[2], bh1[2], bl0[2], bl1[2];
                ldsm_x4(smem_u32(Kh + st + r * QP + c), t0, t1, t2, t3);
                bh0[0] = t0; bh0[1] = t2; bh1[0] = t1; bh1[1] = t3;
                ldsm_x4(smem_u32(Kl + st + r * QP + c), t0, t1, t2, t3);
                bl0[0] = t0; bl0[1] = t2; bl1[0] = t1; bl1[1] = t3;
                mma16816(s[2*p],   ah, bh0);
                mma16816(s[2*p],   ah, bl0);
                mma16816(s[2*p],   al, bh0);
                mma16816(s[2*p+1], ah, bh1);
                mma16816(s[2*p+1], ah, bl1);
                mma16816(s[2*p+1], al, bh1);
            }
        }

        // ---- online softmax
#pragma unroll
        for (int half = 0; half < 2; half++) {
            float rmax = -1e30f;
#pragma unroll
            for (int nt = 0; nt < 8; nt++)
                rmax = fmaxf(rmax, fmaxf(s[nt][2*half], s[nt][2*half + 1]));
            rmax = fmaxf(rmax, __shfl_xor_sync(0xffffffffu, rmax, 1));
            rmax = fmaxf(rmax, __shfl_xor_sync(0xffffffffu, rmax, 2));
            float mnew = fmaxf(m_i[half], rmax);
            float scale = __expf(m_i[half] - mnew);
            float rs = 0.f;
#pragma unroll
            for (int nt = 0; nt < 8; nt++) {
                float p0 = __expf(s[nt][2*half]     - mnew);
                float p1 = __expf(s[nt][2*half + 1] - mnew);
                s[nt][2*half]     = p0;
                s[nt][2*half + 1] = p1;
                rs += p0 + p1;
            }
            rs += __shfl_xor_sync(0xffffffffu, rs, 1);
            rs += __shfl_xor_sync(0xffffffffu, rs, 2);
            l_i[half] = l_i[half] * scale + rs;
            m_i[half] = mnew;
#pragma unroll
            for (int nt = 0; nt < 16; nt++) {
                o[nt][2*half]     *= scale;
                o[nt][2*half + 1] *= scale;
            }
        }

        // ---- O += P V
#pragma unroll
        for (int kk = 0; kk < 4; kk++) {
            uint32_t pah[4], pal[4];
            {
                float v0 = s[2*kk][0],   v1 = s[2*kk][1],   v2 = s[2*kk][2],   v3 = s[2*kk][3];
                float w0 = s[2*kk+1][0], w1 = s[2*kk+1][1], w2 = s[2*kk+1][2], w3 = s[2*kk+1][3];
                __nv_bfloat162 hx;
                float2 f;
                hx = __floats2bfloat162_rn(v0, v1); f = __bfloat1622float2(hx);
                pah[0] = *(uint32_t*)&hx; { __nv_bfloat162 t = __floats2bfloat162_rn(v0 - f.x, v1 - f.y); pal[0] = *(uint32_t*)&t; }
                hx = __floats2bfloat162_rn(v2, v3); f = __bfloat1622float2(hx);
                pah[1] = *(uint32_t*)&hx; { __nv_bfloat162 t = __floats2bfloat162_rn(v2 - f.x, v3 - f.y); pal[1] = *(uint32_t*)&t; }
                hx = __floats2bfloat162_rn(w0, w1); f = __bfloat1622float2(hx);
                pah[2] = *(uint32_t*)&hx; { __nv_bfloat162 t = __floats2bfloat162_rn(w0 - f.x, w1 - f.y); pal[2] = *(uint32_t*)&t; }
                hx = __floats2bfloat162_rn(w2, w3); f = __bfloat1622float2(hx);
                pah[3] = *(uint32_t*)&hx; { __nv_bfloat162 t = __floats2bfloat162_rn(w2 - f.x, w3 - f.y); pal[3] = *(uint32_t*)&t; }
            }
#pragma unroll
            for (int p = 0; p < 8; p++) {
                int r = kk * 16 + (lane & 15);
                int c = p * 16 + ((lane >> 4) * 8);
                uint32_t vh0[2], vh1[2], vl0[2], vl1[2];
                uint32_t t0, t1, t2, t3;
                ldsm_x4_t(smem_u32(Vh + st + r * QP + c), t0, t1, t2, t3);
                vh0[0] = t0; vh0[1] = t1; vh1[0] = t2; vh1[1] = t3;
                ldsm_x4_t(smem_u32(Vl + st + r * QP + c), t0, t1, t2, t3);
                vl0[0] = t0; vl0[1] = t1; vl1[0] = t2; vl1[1] = t3;
                mma16816(o[2*p],   pah, vh0);
                mma16816(o[2*p],   pah, vl0);
                mma16816(o[2*p],   pal, vh0);
                mma16816(o[2*p+1], pah, vh1);
                mma16816(o[2*p+1], pah, vl1);
                mma16816(o[2*p+1], pal, vh1);
            }
        }
    }

    // finalize -> bf16 hi/lo planes of z
    float invl[2] = {1.f / l_i[0], 1.f / l_i[1]};
#pragma unroll
    for (int half = 0; half < 2; half++) {
        size_t row = rowBase + q0 + wid * 16 + (lane >> 2) + half * 8;
#pragma unroll
        for (int nt = 0; nt < 16; nt++) {
            int col = colBase + nt * 8 + (lane & 3) * 2;
            float vx = o[nt][2*half]     * invl[half];
            float vy = o[nt][2*half + 1] * invl[half];
            __nv_bfloat162 hh = __floats2bfloat162_rn(vx, vy);
            float2 f = __bfloat1622float2(hh);
            __nv_bfloat162 ll = __floats2bfloat162_rn(vx - f.x, vy - f.y);
            *(__nv_bfloat162*)(ZH + row * DMODEL + col) = hh;
            *(__nv_bfloat162*)(ZL + row * DMODEL + col) = ll;
        }
    }
}

// ---------------------------------------------------------------------------
extern "C" void kernel_launch(void* const* d_in, const int* in_sizes, int n_in,
                              void* d_out, int out_size)
{
    const float* x     = (const float*)d_in[0];
    const float* W_qkv = (const float*)d_in[1];
    const float* b_qkv = (const float*)d_in[2];
    const float* W_o   = (const float*)d_in[3];
    const float* b_o   = (const float*)d_in[4];
    const float* wq    = (const float*)d_in[5];
    const float* wk    = (const float*)d_in[6];

    float* out   = (float*)d_out;                               // [4096,2048]
    float* k_out = out   + (size_t)MROWS * DMODEL;
    float* v_out = k_out + (size_t)MROWS * DMODEL;

    float* qPtr;
    __nv_bfloat16 *xh, *xl, *Wqh, *Wql, *Woh, *Wol;
    __nv_bfloat16 *qh, *ql, *kh, *kl, *vh, *vl, *zh, *zl;
    cudaGetSymbolAddress((void**)&qPtr, g_q);
    cudaGetSymbolAddress((void**)&xh,  g_xh);  cudaGetSymbolAddress((void**)&xl,  g_xl);
    cudaGetSymbolAddress((void**)&Wqh, g_Wqh); cudaGetSymbolAddress((void**)&Wql, g_Wql);
    cudaGetSymbolAddress((void**)&Woh, g_Woh); cudaGetSymbolAddress((void**)&Wol, g_Wol);
    cudaGetSymbolAddress((void**)&qh,  g_qh);  cudaGetSymbolAddress((void**)&ql,  g_ql);
    cudaGetSymbolAddress((void**)&kh,  g_kh);  cudaGetSymbolAddress((void**)&kl,  g_kl);
    cudaGetSymbolAddress((void**)&vh,  g_vh);  cudaGetSymbolAddress((void**)&vl,  g_vl);
    cudaGetSymbolAddress((void**)&zh,  g_zh);  cudaGetSymbolAddress((void**)&zl,  g_zl);

    // 0) split inputs to bf16 hi/lo planes
    {
        int n4x = MROWS * DMODEL / 4;
        split_kernel<<<(n4x + 255) / 256, 256>>>(x, xh, xl, n4x);
        int n4q = NQKV * DMODEL / 4;
        split_kernel<<<(n4q + 255) / 256, 256>>>(W_qkv, Wqh, Wql, n4q);
        int n4o = DMODEL * DMODEL / 4;
        split_kernel<<<(n4o + 255) / 256, 256>>>(W_o, Woh, Wol, n4o);
    }

    int gemm_smem = 4 * GSTAGES * GTSZ * (int)sizeof(__nv_bfloat16);
    cudaFuncSetAttribute(gemm_planes, cudaFuncAttributeMaxDynamicSharedMemorySize, gemm_smem);

    // 1) QKV projection
    {
        dim3 grid(NQKV / 128, MROWS / 128);
        gemm_planes<<<grid, 256, gemm_smem>>>(xh, xl, Wqh, Wql, b_qkv,
                                              qPtr, k_out, v_out, vh, vl,
                                              MROWS, NQKV, DMODEL, 1);
    }

    // 2) RMS norm q/k -> bf16 planes
    {
        dim3 grid(MROWS * NHEADS, 2);
        rmsnorm_split<<<grid, DHEAD>>>(qPtr, k_out, qh, ql, kh, kl, wq, wk);
    }

    // 3) Attention -> z planes
    {
        int smem = (2 * 128 * QP + 8 * KVT) * (int)sizeof(__nv_bfloat16);
        cudaFuncSetAttribute(attn_tc2, cudaFuncAttributeMaxDynamicSharedMemorySize, smem);
        dim3 grid(SEQ / 128, NHEADS, BATCH);
        attn_tc2<<<grid, 256, smem>>>(qh, ql, kh, kl, vh, vl, zh, zl);
    }

    // 4) Output projection
    {
        dim3 grid(DMODEL / 128, MROWS / 128);
        gemm_planes<<<grid, 256, gemm_smem>>>(zh, zl, Woh, Wol, b_o,
                                              out, nullptr, nullptr, nullptr, nullptr,
                                              MROWS, DMODEL, DMODEL, 0);
    }
}